// round 7
// baseline (speedup 1.0000x reference)
#include <cuda_runtime.h>
#include <cuda_bf16.h>
#include <math.h>
#include <stdint.h>

#define D 128
static constexpr int MAXN = 51200;
static constexpr int MAXMATS = 16;   // slots; last used slot holds Wg frags

// ---------------------------------------------------------------------------
// Scratch (no allocs allowed -> device globals)
// ---------------------------------------------------------------------------
__device__ float d_mj[MAXN * D];
__device__ float d_v [MAXN * D];
// Pre-split, pre-permuted weight images. Per 128x128 matrix: 16384 uint32:
//   [0,8192) hi bf16x2 B-frags, [8192,16384) lo.
// Frag order: word = ((nt*8 + kt)*32 + lane)*2 + ri
//   value = pack_bf16x2(W[k0][n], W[k0+1][n]); n = nt*8+lane/4; k0 = kt*16+2*(lane%4)+ri*8
// Wg (32x128) at slot n_mats: [0,2048) hi, [2048,4096) lo with
//   word = ((nt*2 + kt)*32 + lane)*2 + ri  (kt in 0..1)
__device__ __align__(16) uint32_t d_wimg[MAXMATS * 16384];

__device__ __forceinline__ float sspf(float x) {
    return fmaxf(x, 0.0f) + __logf(1.0f + __expf(-fabsf(x))) - 0.69314718055994530942f;
}

// ---------------------------------------------------------------------------
// HMMA m16n8k16 bf16 (base PTX) + frag building
// ---------------------------------------------------------------------------
__device__ __forceinline__ void mma_bf16(float* d, const uint32_t* a,
                                         uint32_t b0, uint32_t b1) {
    asm volatile(
        "mma.sync.aligned.m16n8k16.row.col.f32.bf16.bf16.f32 "
        "{%0,%1,%2,%3}, {%4,%5,%6,%7}, {%8,%9}, {%0,%1,%2,%3};"
        : "+f"(d[0]), "+f"(d[1]), "+f"(d[2]), "+f"(d[3])
        : "r"(a[0]), "r"(a[1]), "r"(a[2]), "r"(a[3]), "r"(b0), "r"(b1));
}

__device__ __forceinline__ void build_frag(float s0, float s1,
                                           uint32_t& hi, uint32_t& lo) {
    __nv_bfloat162 h2 = __floats2bfloat162_rn(s0, s1);
    float l0 = s0 - __bfloat162float(h2.x);
    float l1 = s1 - __bfloat162float(h2.y);
    __nv_bfloat162 l2 = __floats2bfloat162_rn(l0, l1);
    hi = *reinterpret_cast<uint32_t*>(&h2);
    lo = *reinterpret_cast<uint32_t*>(&l2);
}

// ---------------------------------------------------------------------------
// Weight precompute (8 blocks per matrix for parallelism)
// ---------------------------------------------------------------------------
__global__ void wsplit_kernel(const float* __restrict__ Wj,
                              const float* __restrict__ Wi,
                              const float* __restrict__ Wf,
                              const float* __restrict__ rWint,
                              const float* __restrict__ rWatm,
                              const float* __restrict__ rWout,
                              const float* __restrict__ Wg,
                              int n_int, int n_atom, int n_out) {
    int m    = blockIdx.x >> 3;
    int part = blockIdx.x & 7;
    int n_mats = 3 + n_int + n_atom + n_out;

    if (m == n_mats) {  // Wg [32 x 128]
        uint32_t* hi = d_wimg + (size_t)m * 16384;
        uint32_t* lo = hi + 2048;
        for (int idx = part * 256 + threadIdx.x; idx < 2048; idx += 2048) {
            int ri = idx & 1;
            int l  = (idx >> 1) & 31;
            int f  = idx >> 6;            // nt*2 + kt
            int kt = f & 1, nt = f >> 1;
            int n  = nt * 8 + (l >> 2);
            int k0 = kt * 16 + 2 * (l & 3) + ri * 8;
            uint32_t h, lw;
            build_frag(Wg[k0 * D + n], Wg[(k0 + 1) * D + n], h, lw);
            hi[idx] = h;
            lo[idx] = lw;
        }
        return;
    }

    const float* src;
    if (m == 0)                      src = Wj;
    else if (m == 1)                 src = Wi;
    else if (m == 2)                 src = Wf;
    else if (m < 3 + n_int)          src = rWint + (size_t)(m - 3) * D * D;
    else if (m < 3 + n_int + n_atom) src = rWatm + (size_t)(m - 3 - n_int) * D * D;
    else                             src = rWout + (size_t)(m - 3 - n_int - n_atom) * D * D;

    uint32_t* hi = d_wimg + (size_t)m * 16384;
    uint32_t* lo = hi + 8192;

    for (int idx = part * 1024 + threadIdx.x; idx < (part + 1) * 1024; idx += 256) {
        int ri = idx & 1;
        int l  = (idx >> 1) & 31;
        int f  = idx >> 6;            // nt*8 + kt
        int kt = f & 7, nt = f >> 3;
        int n  = nt * 8 + (l >> 2);
        int k0 = kt * 16 + 2 * (l & 3) + ri * 8;
        uint32_t h, lw;
        build_frag(src[k0 * D + n], src[(k0 + 1) * D + n], h, lw);
        hi[idx] = h;
        lo[idx] = lw;
    }
}

// ---------------------------------------------------------------------------
// MMA stage, weights read straight from global (L1-resident images).
// Pass-separated, 4-nt chunks keep same-acc HMMAs >=4 apart.
// ---------------------------------------------------------------------------
__device__ __forceinline__ void stage_mma_ldg(const uint32_t* __restrict__ img,
                                              int loff,
                                              const uint32_t* ahi, const uint32_t* alo,
                                              float* acc) {
    const char* base = reinterpret_cast<const char*>(img);
    #pragma unroll
    for (int kt = 0; kt < 8; kt++) {
        #pragma unroll
        for (int c = 0; c < 4; c++) {
            uint2 bh[4], bl[4];
            #pragma unroll
            for (int i = 0; i < 4; i++)
                bh[i] = __ldg(reinterpret_cast<const uint2*>(
                    base + ((c * 4 + i) * 8 + kt) * 256 + loff));
            #pragma unroll
            for (int i = 0; i < 4; i++)
                bl[i] = __ldg(reinterpret_cast<const uint2*>(
                    base + 32768 + ((c * 4 + i) * 8 + kt) * 256 + loff));
            #pragma unroll
            for (int i = 0; i < 4; i++)
                mma_bf16(acc + (c * 4 + i) * 4, ahi + kt * 4, bh[i].x, bh[i].y);
            #pragma unroll
            for (int i = 0; i < 4; i++)
                mma_bf16(acc + (c * 4 + i) * 4, alo + kt * 4, bh[i].x, bh[i].y);
            #pragma unroll
            for (int i = 0; i < 4; i++)
                mma_bf16(acc + (c * 4 + i) * 4, ahi + kt * 4, bl[i].x, bl[i].y);
        }
    }
}

// ---------------------------------------------------------------------------
// Head kernel: A = ssp(x); mj = ssp(A@Wj+bj); v = ssp(A@Wi+bi)
// 64-row tiles, 128 threads, 2 CTAs/SM, no smem.
// ---------------------------------------------------------------------------
__global__ void __launch_bounds__(128, 2)
tc_head_kernel(const float* __restrict__ x,
               const float* __restrict__ bj, const float* __restrict__ bi,
               float* __restrict__ mj, float* __restrict__ v, int N) {
    const int t = threadIdx.x, w = t >> 5, l = t & 31;
    const int g = l >> 2, m4 = l & 3;
    const int loff = l * 8;
    const int row_lo = blockIdx.x * 64 + w * 16 + g;
    const int row_hi = row_lo + 8;
    const int cb = 2 * m4;

    uint32_t ahi[32], alo[32];
    #pragma unroll
    for (int nt = 0; nt < 16; nt++) {
        int c0 = nt * 8 + cb;
        float2 a = (row_lo < N) ? *reinterpret_cast<const float2*>(x + (size_t)row_lo * D + c0)
                                : make_float2(0.f, 0.f);
        float2 b = (row_hi < N) ? *reinterpret_cast<const float2*>(x + (size_t)row_hi * D + c0)
                                : make_float2(0.f, 0.f);
        int base = (nt >> 1) * 4 + (nt & 1) * 2;
        build_frag(sspf(a.x), sspf(a.y), ahi[base], alo[base]);
        build_frag(sspf(b.x), sspf(b.y), ahi[base + 1], alo[base + 1]);
    }

    #pragma unroll
    for (int s = 0; s < 2; s++) {
        const uint32_t* img = d_wimg + (size_t)s * 16384;
        const float* bias = s ? bi : bj;
        float acc[64];
        #pragma unroll
        for (int i = 0; i < 64; i++) acc[i] = 0.0f;
        stage_mma_ldg(img, loff, ahi, alo, acc);

        float* outp = s ? v : mj;
        #pragma unroll
        for (int nt = 0; nt < 16; nt++) {
            int c0 = nt * 8 + cb;
            float2 bv = __ldg(reinterpret_cast<const float2*>(bias + c0));
            float s0 = sspf(acc[nt * 4 + 0] + bv.x);
            float s1 = sspf(acc[nt * 4 + 1] + bv.y);
            float s2 = sspf(acc[nt * 4 + 2] + bv.x);
            float s3 = sspf(acc[nt * 4 + 3] + bv.y);
            if (row_lo < N)
                *reinterpret_cast<float2*>(outp + (size_t)row_lo * D + c0) = make_float2(s0, s1);
            if (row_hi < N)
                *reinterpret_cast<float2*>(outp + (size_t)row_hi * D + c0) = make_float2(s2, s3);
        }
    }
}

// ---------------------------------------------------------------------------
// Tail kernel: register-chained stage loop; weights via __ldg (L1), no smem.
// 64-row tiles, 128 threads, 2 CTAs/SM.
// ---------------------------------------------------------------------------
__global__ void __launch_bounds__(128, 2)
tc_tail_kernel(const float* __restrict__ v_in, const float* __restrict__ x,
               const float* __restrict__ u,
               const float* __restrict__ rbint, const float* __restrict__ bf,
               const float* __restrict__ rbatm, const float* __restrict__ rbout,
               int n_int, int n_atom, int n_out,
               float* __restrict__ h_out, float* __restrict__ o_out, int N) {
    const int t = threadIdx.x, w = t >> 5, l = t & 31;
    const int g = l >> 2, m4 = l & 3;
    const int loff = l * 8;
    const int row_lo = blockIdx.x * 64 + w * 16 + g;
    const int row_hi = row_lo + 8;
    const int cb = 2 * m4;

    const int total = 2 * n_int + 1 + 2 * n_atom + 2 * n_out;

    auto stage_desc = [&](int s, int& mat, const float*& bias, int& mode, bool& storeh) {
        storeh = false;
        if (s < 2 * n_int) {
            mat = 3 + (s >> 1); bias = rbint + (size_t)(s >> 1) * D;
            mode = (s & 1) ? 1 : 0;
        } else if (s == 2 * n_int) {
            mat = 2; bias = bf; mode = 2; storeh = (n_atom == 0);
        } else {
            int s2 = s - 2 * n_int - 1;
            if (s2 < 2 * n_atom) {
                mat = 3 + n_int + (s2 >> 1); bias = rbatm + (size_t)(s2 >> 1) * D;
                mode = (s2 & 1) ? 1 : 0;
                storeh = (s2 == 2 * n_atom - 1);
            } else {
                int s3 = s2 - 2 * n_atom;
                mat = 3 + n_int + n_atom + (s3 >> 1); bias = rbout + (size_t)(s3 >> 1) * D;
                mode = (s3 & 1) ? ((s3 == 2 * n_out - 1) ? 3 : 1) : 0;
            }
        }
    };

    // init fragments + residual carry
    float vr[64];
    uint32_t ahi[32], alo[32];
    #pragma unroll
    for (int nt = 0; nt < 16; nt++) {
        int c0 = nt * 8 + cb;
        float2 a = (row_lo < N) ? *reinterpret_cast<const float2*>(v_in + (size_t)row_lo * D + c0)
                                : make_float2(0.f, 0.f);
        float2 b = (row_hi < N) ? *reinterpret_cast<const float2*>(v_in + (size_t)row_hi * D + c0)
                                : make_float2(0.f, 0.f);
        vr[nt * 4 + 0] = a.x; vr[nt * 4 + 1] = a.y;
        vr[nt * 4 + 2] = b.x; vr[nt * 4 + 3] = b.y;
        int base = (nt >> 1) * 4 + (nt & 1) * 2;
        build_frag(sspf(a.x), sspf(a.y), ahi[base], alo[base]);
        build_frag(sspf(b.x), sspf(b.y), ahi[base + 1], alo[base + 1]);
    }

    for (int s = 0; s < total; s++) {
        int mat; const float* bias; int mode; bool storeh;
        stage_desc(s, mat, bias, mode, storeh);
        const uint32_t* img = d_wimg + (size_t)mat * 16384;

        float acc[64];
        #pragma unroll
        for (int i = 0; i < 64; i++) acc[i] = 0.0f;
        stage_mma_ldg(img, loff, ahi, alo, acc);

        #pragma unroll
        for (int nt = 0; nt < 16; nt++) {
            int c0 = nt * 8 + cb;
            float2 bv = __ldg(reinterpret_cast<const float2*>(bias + c0));
            float v0 = acc[nt * 4 + 0] + bv.x;
            float v1 = acc[nt * 4 + 1] + bv.y;
            float v2 = acc[nt * 4 + 2] + bv.x;
            float v3 = acc[nt * 4 + 3] + bv.y;
            if (mode == 1 || mode == 3) {
                v0 += vr[nt * 4 + 0]; v1 += vr[nt * 4 + 1];
                v2 += vr[nt * 4 + 2]; v3 += vr[nt * 4 + 3];
            }
            if (mode == 2) {
                float2 xl = (row_lo < N) ? *reinterpret_cast<const float2*>(x + (size_t)row_lo * D + c0)
                                         : make_float2(0.f, 0.f);
                float2 xh = (row_hi < N) ? *reinterpret_cast<const float2*>(x + (size_t)row_hi * D + c0)
                                         : make_float2(0.f, 0.f);
                float2 uv = __ldg(reinterpret_cast<const float2*>(u + c0));
                v0 += uv.x * sspf(xl.x); v1 += uv.y * sspf(xl.y);
                v2 += uv.x * sspf(xh.x); v3 += uv.y * sspf(xh.y);
            }
            if (mode == 1 || mode == 2) {
                vr[nt * 4 + 0] = v0; vr[nt * 4 + 1] = v1;
                vr[nt * 4 + 2] = v2; vr[nt * 4 + 3] = v3;
            }
            float s0 = sspf(v0), s1 = sspf(v1), s2 = sspf(v2), s3 = sspf(v3);
            if (mode == 3) {
                if (row_lo < N)
                    *reinterpret_cast<float2*>(o_out + (size_t)row_lo * D + c0) = make_float2(s0, s1);
                if (row_hi < N)
                    *reinterpret_cast<float2*>(o_out + (size_t)row_hi * D + c0) = make_float2(s2, s3);
            } else {
                int base = (nt >> 1) * 4 + (nt & 1) * 2;
                build_frag(s0, s1, ahi[base], alo[base]);
                build_frag(s2, s3, ahi[base + 1], alo[base + 1]);
            }
        }

        if (storeh) {
            #pragma unroll
            for (int nt = 0; nt < 16; nt++) {
                int c0 = nt * 8 + cb;
                if (row_lo < N)
                    *reinterpret_cast<float2*>(h_out + (size_t)row_lo * D + c0) =
                        make_float2(vr[nt * 4 + 0], vr[nt * 4 + 1]);
                if (row_hi < N)
                    *reinterpret_cast<float2*>(h_out + (size_t)row_hi * D + c0) =
                        make_float2(vr[nt * 4 + 2], vr[nt * 4 + 3]);
            }
        }
        __syncthreads();   // keep warps in step for L1 weight reuse
    }
}

// ---------------------------------------------------------------------------
// Edge kernel (HMMA gate): one warp processes 16 edges; scatter via red.v4
// after packing 4 columns per even lane with one lane-XOR shuffle.
// ---------------------------------------------------------------------------
__global__ __launch_bounds__(256)
void edge_mma_kernel(const float* __restrict__ g,
                     const int* __restrict__ idx_i,
                     const int* __restrict__ idx_j,
                     const float* __restrict__ mj,
                     float* __restrict__ v,
                     int E, int wg_slot) {
    __shared__ uint32_t wgs[4096];   // Wg frags: hi[2048] + lo[2048]
    {
        const uint4* src = reinterpret_cast<const uint4*>(d_wimg + (size_t)wg_slot * 16384);
        uint4* dst = reinterpret_cast<uint4*>(wgs);
        #pragma unroll
        for (int i = threadIdx.x; i < 1024; i += 256)
            dst[i] = src[i];
    }
    __syncthreads();

    const int t = threadIdx.x, l = t & 31;
    const int gq = l >> 2, m4 = l & 3;
    const int batch = blockIdx.x * 8 + (t >> 5);
    const int e0 = batch * 16;
    if (e0 >= E) return;

    const int r0 = e0 + gq, r1 = r0 + 8;
    const bool v0ok = (r0 < E), v1ok = (r1 < E);
    const int j0 = v0ok ? __ldg(idx_j + r0) : 0;
    const int i0 = v0ok ? __ldg(idx_i + r0) : 0;
    const int j1 = v1ok ? __ldg(idx_j + r1) : 0;
    const int i1 = v1ok ? __ldg(idx_i + r1) : 0;

    // A fragments from g rows (R=32 -> 2 ktiles)
    uint32_t ahi[8], alo[8];
    #pragma unroll
    for (int kt = 0; kt < 2; kt++) {
        int kb = kt * 16 + 2 * m4;
        float2 p00 = v0ok ? *reinterpret_cast<const float2*>(g + (size_t)r0 * 32 + kb)
                          : make_float2(0.f, 0.f);
        float2 p01 = v0ok ? *reinterpret_cast<const float2*>(g + (size_t)r0 * 32 + kb + 8)
                          : make_float2(0.f, 0.f);
        float2 p10 = v1ok ? *reinterpret_cast<const float2*>(g + (size_t)r1 * 32 + kb)
                          : make_float2(0.f, 0.f);
        float2 p11 = v1ok ? *reinterpret_cast<const float2*>(g + (size_t)r1 * 32 + kb + 8)
                          : make_float2(0.f, 0.f);
        build_frag(p00.x, p00.y, ahi[kt * 4 + 0], alo[kt * 4 + 0]);
        build_frag(p10.x, p10.y, ahi[kt * 4 + 1], alo[kt * 4 + 1]);
        build_frag(p01.x, p01.y, ahi[kt * 4 + 2], alo[kt * 4 + 2]);
        build_frag(p11.x, p11.y, ahi[kt * 4 + 3], alo[kt * 4 + 3]);
    }

    float acc[64];
    #pragma unroll
    for (int i = 0; i < 64; i++) acc[i] = 0.0f;

    const char* base = reinterpret_cast<const char*>(wgs);
    const int loff = l * 8;
    #pragma unroll
    for (int nt = 0; nt < 16; nt++) {
        #pragma unroll
        for (int kt = 0; kt < 2; kt++) {
            uint2 bh = *reinterpret_cast<const uint2*>(base + (nt * 2 + kt) * 256 + loff);
            mma_bf16(acc + nt * 4, ahi + kt * 4, bh.x, bh.y);
            mma_bf16(acc + nt * 4, alo + kt * 4, bh.x, bh.y);
            uint2 bl = *reinterpret_cast<const uint2*>(base + 8192 + (nt * 2 + kt) * 256 + loff);
            mma_bf16(acc + nt * 4, ahi + kt * 4, bl.x, bl.y);
        }
    }

    // scatter: v[i,:] += gate * mj[j,:]  (pack 4 cols into even lanes, red.v4)
    const bool evenlane = ((l & 1) == 0);
    #pragma unroll
    for (int nt = 0; nt < 16; nt++) {
        int c0 = nt * 8 + 2 * m4;
        float p0 = 0.f, p1 = 0.f, p2 = 0.f, p3 = 0.f;
        if (v0ok) {
            float2 m0 = *reinterpret_cast<const float2*>(mj + (size_t)j0 * D + c0);
            p0 = acc[nt * 4 + 0] * m0.x;
            p1 = acc[nt * 4 + 1] * m0.y;
        }
        if (v1ok) {
            float2 m1 = *reinterpret_cast<const float2*>(mj + (size_t)j1 * D + c0);
            p2 = acc[nt * 4 + 2] * m1.x;
            p3 = acc[nt * 4 + 3] * m1.y;
        }
        float q0 = __shfl_xor_sync(0xffffffffu, p0, 1);
        float q1 = __shfl_xor_sync(0xffffffffu, p1, 1);
        float q2 = __shfl_xor_sync(0xffffffffu, p2, 1);
        float q3 = __shfl_xor_sync(0xffffffffu, p3, 1);
        if (evenlane) {
            if (v0ok)
                asm volatile("red.global.add.v4.f32 [%0], {%1, %2, %3, %4};"
                             :: "l"(v + (size_t)i0 * D + c0), "f"(p0), "f"(p1), "f"(q0), "f"(q1)
                             : "memory");
            if (v1ok)
                asm volatile("red.global.add.v4.f32 [%0], {%1, %2, %3, %4};"
                             :: "l"(v + (size_t)i1 * D + c0), "f"(p2), "f"(p3), "f"(q2), "f"(q3)
                             : "memory");
        }
    }
}

// ---------------------------------------------------------------------------
// Host-side dispatch
// ---------------------------------------------------------------------------
extern "C" void kernel_launch(void* const* d_in, const int* in_sizes, int n_in,
                              void* d_out, int out_size) {
    const float* x     = (const float*)d_in[0];
    const float* g_ij  = (const float*)d_in[1];
    const float* Wf    = (const float*)d_in[2];
    const float* bf    = (const float*)d_in[3];
    const float* Wg    = (const float*)d_in[4];
    const float* Wj    = (const float*)d_in[5];
    const float* bj    = (const float*)d_in[6];
    const float* Wi    = (const float*)d_in[7];
    const float* bi    = (const float*)d_in[8];
    const float* u     = (const float*)d_in[9];
    const float* rWint = (const float*)d_in[10];
    const float* rbint = (const float*)d_in[11];
    const float* rWatm = (const float*)d_in[12];
    const float* rbatm = (const float*)d_in[13];
    const float* rWout = (const float*)d_in[14];
    const float* rbout = (const float*)d_in[15];
    const int*   idx_i = (const int*)d_in[16];
    const int*   idx_j = (const int*)d_in[17];

    const int N      = in_sizes[0] / D;
    const int E      = in_sizes[16];
    const int n_int  = in_sizes[11] / D;
    const int n_atom = in_sizes[13] / D;
    const int n_out  = in_sizes[15] / D;

    if (N > MAXN) return;
    const int n_mats = 3 + n_int + n_atom + n_out;
    if (n_mats + 1 > MAXMATS) return;

    float *mj, *v;
    cudaGetSymbolAddress((void**)&mj, d_mj);
    cudaGetSymbolAddress((void**)&v,  d_v);

    float* o_out = (float*)d_out;                 // o -> first N*D
    float* h_out = (float*)d_out + (size_t)N * D; // h -> second N*D

    const int tiles64 = (N + 63) / 64;

    // 0) split + permute weights (incl. Wg at slot n_mats)
    wsplit_kernel<<<(n_mats + 1) * 8, 256>>>(Wj, Wi, Wf, rWint, rWatm, rWout, Wg,
                                             n_int, n_atom, n_out);

    // 1) mj = ssp(ssp(x)@Wj+bj); v = ssp(ssp(x)@Wi+bi)
    tc_head_kernel<<<tiles64, 128>>>(x, bj, bi, mj, v, N);

    // 2) v += segment_sum( (g_ij @ Wg) * mj[idx_j], idx_i )   [HMMA gate]
    {
        int batches = (E + 15) / 16;
        int blocks  = (batches + 7) / 8;
        edge_mma_kernel<<<blocks, 256>>>(g_ij, idx_i, idx_j, mj, v, E, n_mats);
    }

    // 3) fused register-chained tail, weights via L1
    tc_tail_kernel<<<tiles64, 128>>>(
        v, x, u, rbint, bf, rbatm, rbout, n_int, n_atom, n_out, h_out, o_out, N);
}